// round 12
// baseline (speedup 1.0000x reference)
#include <cuda_runtime.h>
#include <cuda_bf16.h>
#include <math.h>

#define KC 64
#define DD 128
#define NN 4096
#define NB 32
#define NT 512
#define GRID (NN / NB)   // 128 blocks: one per SM, single balanced wave
#define MPAD 129

#define LN2F 0.6931471805599453f
#define LOG2PIF 1.8378770664093453f
#define LGAMMA64F 201.00931639928152f

// ---------------- device scratch (zero-init; self-resetting each run) ----------------
__device__ __align__(16) float g_numer[KC * KC];   // sum of (ln2 - softplus)
__device__ __align__(16) float g_dsum[KC * KC];    // sum over class i of (L[n][j] - logC_j) = kap_j * sum(fhat.mu_j)
__device__ float g_counts[KC];
__device__ float g_rank;
__device__ float g_js;
__device__ int   g_arrive;
__device__ int   g_done;

__device__ __forceinline__ float softplus_precise(float x) {
    return (x > 0.0f) ? (x + log1pf(expf(-x))) : log1pf(expf(x));
}

// log1p(t), t in [0,1]: Taylor at t=0.5, deg 11, |err| < 2e-7. Pure FFMA.
__device__ __forceinline__ float log1p_poly(float t) {
    float s = t - 0.5f;
    float p = -0.0017337974f + 0.0010507863f * s;
    p = fmaf(p, s,  0.0028896624f);
    p = fmaf(p, s, -0.0048773053f);
    p = fmaf(p, s,  0.0083610948f);
    p = fmaf(p, s, -0.0146319159f);
    p = fmaf(p, s,  0.0263374486f);
    p = fmaf(p, s, -0.0493827160f);
    p = fmaf(p, s,  0.0987654321f);
    p = fmaf(p, s, -0.2222222222f);
    p = fmaf(p, s,  0.6666666667f);
    p = fmaf(p, s,  0.4054651081f);
    return p;
}

__device__ __forceinline__ void red_v4(float* gptr, float a, float b, float c, float d) {
    unsigned long long ga = (unsigned long long)__cvta_generic_to_global(gptr);
    asm volatile("red.global.add.v4.f32 [%0], {%1, %2, %3, %4};"
                 :: "l"(ga), "f"(a), "f"(b), "f"(c), "f"(d) : "memory");
}

struct __align__(16) Smem {
    float mus[KC * MPAD];        // raw mus, padded (33024B)
    float f[NB][DD];             // features (16KB) — post-barrier scratch
    float L[NB][KC];             // logits (8KB)    — pre-barrier pdu scratch
    float lc[KC];                // 16B-aligned for float4 reads
    float invmu[KC], kap[KC];
    float invn[NB];
    float musq[8][KC];
    float dotu_s[KC];            // mu_i . mu_j (normalized); persists across barrier
    int   lab[NB];
};

__global__ void __launch_bounds__(NT) k_fused(const float* __restrict__ feat,
                                              const float* __restrict__ musp,
                                              const float* __restrict__ rho,
                                              const int* __restrict__ lab32,
                                              float* __restrict__ out) {
    extern __shared__ char smem_raw[];
    Smem* s = (Smem*)smem_raw;
    int tid = threadIdx.x;
    int bid = blockIdx.x;
    int n0 = bid * NB;

    // labels dtype probe (odd int32 words nonzero => int32 labels)
    int pred = (lab32[2 * tid + 1] != 0);

    // load mus_param coalesced -> padded rows
    {
        const float4* msrc = (const float4*)musp;
#pragma unroll
        for (int r = 0; r < 4; r++) {
            int idx = tid + NT * r;
            float4 v = msrc[idx];
            int k = idx >> 5, d = (idx & 31) * 4;
            float* p = &s->mus[k * MPAD + d];
            p[0] = v.x; p[1] = v.y; p[2] = v.z; p[3] = v.w;
        }
    }
    // load 32x128 features
    {
        const float4* src = (const float4*)(feat + n0 * DD);
        float4* dst = (float4*)&s->f[0][0];
        dst[tid]      = src[tid];
        dst[tid + NT] = src[tid + NT];
    }
    int anyodd = __syncthreads_or(pred);
    int shift = anyodd ? 0 : 1;

    if (tid < NB) {
        int l = lab32[(n0 + tid) << shift];
        s->lab[tid] = min(max(l, 0), KC - 1);
    }

    // mus squared-norm partials
    {
        int k = tid & 63, q = tid >> 6;
        float sm = 0.0f;
        const float* p = &s->mus[k * MPAD + q * 16];
#pragma unroll
        for (int r = 0; r < 16; r++) { float m = p[r]; sm += m * m; }
        s->musq[q][k] = sm;
    }
    // feature norms: warp w handles rows 2w, 2w+1
    {
        int w = tid >> 5, lane = tid & 31;
#pragma unroll
        for (int rr = 0; rr < 2; rr++) {
            int r = 2 * w + rr;
            float sm = 0.0f;
#pragma unroll
            for (int c = 0; c < 4; c++) {
                float x = s->f[r][lane + 32 * c];
                sm += x * x;
            }
#pragma unroll
            for (int o = 16; o > 0; o >>= 1) sm += __shfl_xor_sync(0xffffffffu, sm, o);
            if (lane == 0) s->invn[r] = 1.0f / fmaxf(sqrtf(sm), 1e-12f);
        }
    }
    __syncthreads();

    // per-class scalars
    if (tid < KC) {
        float sm = 0.0f;
#pragma unroll
        for (int q = 0; q < 8; q++) sm += s->musq[q][tid];
        s->invmu[tid] = 1.0f / fmaxf(sqrtf(sm), 1e-12f);
        float r = rho[tid];
        float kap = fmaxf(softplus_precise(r), 1e-6f);
        s->kap[tid] = kap;
        float logI = (kap < 1e-3f)
                   ? 63.0f * logf(kap * 0.5f + 1e-12f) - LGAMMA64F
                   : kap - 0.5f * logf(6.283185307179586f * kap + 1e-12f);
        s->lc[tid] = -63.0f * logf(kap + 1e-12f) - 64.0f * LOG2PIF - logI;
    }
    if (tid < NB) atomicAdd(&g_counts[s->lab[tid]], 1.0f);
    __syncthreads();

    // L = logC + kappa*invmu*invn*(f . mu_raw); 8 groups x 4 samples
    int g = tid >> 6;
    int k = tid & 63;
    {
        float acc0 = 0.f, acc1 = 0.f, acc2 = 0.f, acc3 = 0.f;
        const float4* f0 = (const float4*)&s->f[g * 4 + 0][0];
        const float4* f1 = (const float4*)&s->f[g * 4 + 1][0];
        const float4* f2 = (const float4*)&s->f[g * 4 + 2][0];
        const float4* f3 = (const float4*)&s->f[g * 4 + 3][0];
        const float* mrow = &s->mus[k * MPAD];
#pragma unroll
        for (int d4 = 0; d4 < DD / 4; d4++) {
            float m0 = mrow[4 * d4 + 0];
            float m1 = mrow[4 * d4 + 1];
            float m2 = mrow[4 * d4 + 2];
            float m3 = mrow[4 * d4 + 3];
            float4 x0 = f0[d4], x1 = f1[d4], x2 = f2[d4], x3 = f3[d4];
            acc0 += m0 * x0.x + m1 * x0.y + m2 * x0.z + m3 * x0.w;
            acc1 += m0 * x1.x + m1 * x1.y + m2 * x1.z + m3 * x1.w;
            acc2 += m0 * x2.x + m1 * x2.y + m2 * x2.z + m3 * x2.w;
            acc3 += m0 * x3.x + m1 * x3.y + m2 * x3.z + m3 * x3.w;
        }
        float sk = s->kap[k] * s->invmu[k], lc = s->lc[k];
        s->L[g * 4 + 0][k] = lc + sk * s->invn[g * 4 + 0] * acc0;
        s->L[g * 4 + 1][k] = lc + sk * s->invn[g * 4 + 1] * acc1;
        s->L[g * 4 + 2][k] = lc + sk * s->invn[g * 4 + 2] * acc2;
        s->L[g * 4 + 3][k] = lc + sk * s->invn[g * 4 + 3] * acc3;
    }
    __syncthreads();

    // numer + dsum: thread -> (n = tid>>4, k-quad); float4 L/lc reads, two v4 REDG
    {
        int n = tid >> 4;
        int k0 = (tid & 15) * 4;
        float4 Lv  = *(const float4*)&s->L[n][k0];
        float4 lcv = *(const float4*)&s->lc[k0];
        float Li = s->L[n][s->lab[n]];
        float Lr[4] = {Lv.x, Lv.y, Lv.z, Lv.w};
        float lcr[4] = {lcv.x, lcv.y, lcv.z, lcv.w};
        float vn[4], vd[4];
#pragma unroll
        for (int c = 0; c < 4; c++) {
            float x = Lr[c] - Li;
            float t = __expf(-fabsf(x));
            vn[c] = LN2F - (log1p_poly(t) + fmaxf(x, 0.0f));
            vd[c] = Lr[c] - lcr[c];           // kap_j * (fhat . mu_j), O(1)
        }
        int row = s->lab[n] * KC + k0;
        red_v4(&g_numer[row], vn[0], vn[1], vn[2], vn[3]);
        red_v4(&g_dsum[row],  vd[0], vd[1], vd[2], vd[3]);
    }

    // ---------------- arrive at grid barrier ----------------
    __threadfence();
    __syncthreads();
    if (tid == 0) atomicAdd(&g_arrive, 1);
    if (bid >= KC) return;

    // ---- pre-barrier epilogue work: dotu = mu_i . mu_j (mus-only, overlap with stragglers) ----
    int i = bid;
    {
        int j = tid & 63, q = tid >> 6;
        float du = 0.0f;
        const float* mi = &s->mus[i * MPAD + q * 16];
        const float* mj = &s->mus[j * MPAD + q * 16];
#pragma unroll
        for (int r = 0; r < 16; r++) du += mi[r] * mj[r];
        ((float(*)[KC])&s->L[0][0])[q][j] = du;    // pdu scratch in L region
    }
    __syncthreads();
    if (tid < KC) {
        float (*pdu)[KC] = (float(*)[KC])&s->L[0][0];
        float du = 0.0f;
#pragma unroll
        for (int q = 0; q < 8; q++) du += pdu[q][tid];
        s->dotu_s[tid] = du * s->invmu[i] * s->invmu[tid];
    }

    // ---------------- grid barrier wait ----------------
    if (tid == 0) {
        volatile int* va = &g_arrive;
        while (*va < GRID) { }
    }
    __syncthreads();
    __threadfence();

    // ---------------- tiny post-barrier tail ----------------
    float* ep   = &s->f[0][0];
    float* cnts = ep;            // 64
    float* numr = ep + 64;       // 64
    float* dsum = ep + 128;      // 64
    float* dotm = ep + 192;      // 64
    float* redr = ep + 256;
    float* redj = ep + 320;

    if (tid < KC) {
        cnts[tid] = g_counts[tid];
        numr[tid] = g_numer[i * KC + tid];
    } else if (tid < 2 * KC) {
        dsum[tid - KC] = g_dsum[i * KC + (tid - KC)];
    }
    __syncthreads();
    // self-reset rows owned by this block
    if (tid < KC) g_numer[i * KC + tid] = 0.0f;
    else if (tid < 2 * KC) g_dsum[i * KC + (tid - KC)] = 0.0f;

    float cnt_i = cnts[i];
    bool zi = (cnt_i == 0.0f);
    float cs = fmaxf(cnt_i, 1.0f);
    if (tid < KC)
        dotm[tid] = zi ? s->dotu_s[tid] : dsum[tid] / (cs * s->kap[tid]);
    __syncthreads();

    if (tid < KC) {
        int j = tid;
        float diff = s->kap[i] * dotm[i] - s->kap[j] * dotm[j];
        float h = (j != i) ? fmaxf(0.5f * fabsf((float)(i - j)) - diff, 0.0f) / cs : 0.0f;
        float cnt_j = cnts[j];
        bool zp = zi || (cnt_j == 0.0f);
        float wgt = (i == j) ? 0.0f : fabsf((float)(i - j));
        float contrib;
        if (zp) {
            float ki = s->kap[i], kj = s->kap[j];
            float kci = fmaxf(ki, 1e-8f), kcj = fmaxf(kj, 1e-8f);
            float Ai = (kci > 50.0f) ? (1.0f - 127.0f / (2.0f * kci)) : (kci / 128.0f);
            float Aj = (kcj > 50.0f) ? (1.0f - 127.0f / (2.0f * kcj)) : (kcj / 128.0f);
            float du = s->dotu_s[j];
            contrib = wgt * 0.5f * (Ai * (ki - kj * du) + Aj * (kj - ki * du));
        } else {
            contrib = wgt * numr[j] / cs;   // symmetry-folded JS
        }
        redr[j] = h;
        redj[j] = contrib;
    }
    __syncthreads();
    if (tid < 32) {
        float r = redr[tid] + redr[tid + 32];
        float jj = redj[tid] + redj[tid + 32];
#pragma unroll
        for (int o = 16; o > 0; o >>= 1) {
            r  += __shfl_xor_sync(0xffffffffu, r, o);
            jj += __shfl_xor_sync(0xffffffffu, jj, o);
        }
        if (tid == 0) {
            atomicAdd(&g_rank, r);
            atomicAdd(&g_js, jj);
            __threadfence();
            if (atomicAdd(&g_done, 1) == KC - 1) {
                float rr = atomicAdd(&g_rank, 0.0f);
                float ss = atomicAdd(&g_js, 0.0f);
                out[0] = rr / (4096.0f + 1e-9f) + ss / (87360.0f + 1e-9f);
                for (int c = 0; c < KC; c++) g_counts[c] = 0.0f;
                g_rank = 0.0f; g_js = 0.0f; g_done = 0; g_arrive = 0;
            }
        }
    }
}

extern "C" void kernel_launch(void* const* d_in, const int* in_sizes, int n_in,
                              void* d_out, int out_size) {
    const float* features  = (const float*)d_in[0];
    const float* mus_param = (const float*)d_in[1];
    const float* rho_kappa = (const float*)d_in[2];
    const int*   labels32  = (const int*)d_in[3];
    float* out = (float*)d_out;

    cudaFuncSetAttribute(k_fused, cudaFuncAttributeMaxDynamicSharedMemorySize,
                         (int)sizeof(Smem));
    k_fused<<<GRID, NT, sizeof(Smem)>>>(features, mus_param, rho_kappa, labels32, out);
}

// round 13
// speedup vs baseline: 1.0107x; 1.0107x over previous
#include <cuda_runtime.h>
#include <cuda_bf16.h>
#include <math.h>

#define KC 64
#define DD 128
#define NN 4096
#define NB 32
#define NT 512
#define GRID (NN / NB)   // 128 blocks: one per SM, single balanced wave
#define MPAD 129

#define LN2F 0.6931471805599453f
#define LOG2PIF 1.8378770664093453f
#define LGAMMA64F 201.00931639928152f

// ---------------- device scratch (zero-init; self-resetting each run) ----------------
__device__ __align__(16) float g_numer[KC * KC];   // sum of (ln2 - softplus)
__device__ __align__(16) float g_dsum[KC * KC];    // sum over class i of kap_j*(fhat.mu_j)
__device__ float g_counts[KC];
__device__ int   g_arrive;

__device__ __forceinline__ float softplus_precise(float x) {
    return (x > 0.0f) ? (x + log1pf(expf(-x))) : log1pf(expf(x));
}

// log1p(t), t in [0,1]: Taylor at t=0.5, deg 11, |err| < 2e-7. Pure FFMA.
__device__ __forceinline__ float log1p_poly(float t) {
    float s = t - 0.5f;
    float p = -0.0017337974f + 0.0010507863f * s;
    p = fmaf(p, s,  0.0028896624f);
    p = fmaf(p, s, -0.0048773053f);
    p = fmaf(p, s,  0.0083610948f);
    p = fmaf(p, s, -0.0146319159f);
    p = fmaf(p, s,  0.0263374486f);
    p = fmaf(p, s, -0.0493827160f);
    p = fmaf(p, s,  0.0987654321f);
    p = fmaf(p, s, -0.2222222222f);
    p = fmaf(p, s,  0.6666666667f);
    p = fmaf(p, s,  0.4054651081f);
    return p;
}

__device__ __forceinline__ void red_v4(float* gptr, float a, float b, float c, float d) {
    unsigned long long ga = (unsigned long long)__cvta_generic_to_global(gptr);
    asm volatile("red.global.add.v4.f32 [%0], {%1, %2, %3, %4};"
                 :: "l"(ga), "f"(a), "f"(b), "f"(c), "f"(d) : "memory");
}

struct __align__(16) Smem {
    float mus[KC * MPAD];        // raw mus, padded — epilogue dsum overlay (first 16KB)
    float f[NB][DD];             // features (16KB) — epilogue numer overlay
    float L[NB][KC];             // logits (8KB)    — epilogue per-row scratch
    float lc[KC];
    float invmu[KC], kap[KC];
    float invn[NB];
    float musq[8][KC];
    int   lab[NB];
    int   is_last;
};

__global__ void __launch_bounds__(NT) k_fused(const float* __restrict__ feat,
                                              const float* __restrict__ musp,
                                              const float* __restrict__ rho,
                                              const int* __restrict__ lab32,
                                              float* __restrict__ out) {
    extern __shared__ char smem_raw[];
    Smem* s = (Smem*)smem_raw;
    int tid = threadIdx.x;
    int bid = blockIdx.x;
    int n0 = bid * NB;

    // labels dtype probe (odd int32 words nonzero => int32 labels)
    int pred = (lab32[2 * tid + 1] != 0);

    // load mus_param coalesced -> padded rows
    {
        const float4* msrc = (const float4*)musp;
#pragma unroll
        for (int r = 0; r < 4; r++) {
            int idx = tid + NT * r;
            float4 v = msrc[idx];
            int k = idx >> 5, d = (idx & 31) * 4;
            float* p = &s->mus[k * MPAD + d];
            p[0] = v.x; p[1] = v.y; p[2] = v.z; p[3] = v.w;
        }
    }
    // load 32x128 features
    {
        const float4* src = (const float4*)(feat + n0 * DD);
        float4* dst = (float4*)&s->f[0][0];
        dst[tid]      = src[tid];
        dst[tid + NT] = src[tid + NT];
    }
    int anyodd = __syncthreads_or(pred);
    int shift = anyodd ? 0 : 1;

    if (tid < NB) {
        int l = lab32[(n0 + tid) << shift];
        s->lab[tid] = min(max(l, 0), KC - 1);
    }

    // mus squared-norm partials
    {
        int k = tid & 63, q = tid >> 6;
        float sm = 0.0f;
        const float* p = &s->mus[k * MPAD + q * 16];
#pragma unroll
        for (int r = 0; r < 16; r++) { float m = p[r]; sm += m * m; }
        s->musq[q][k] = sm;
    }
    // feature norms: warp w handles rows 2w, 2w+1
    {
        int w = tid >> 5, lane = tid & 31;
#pragma unroll
        for (int rr = 0; rr < 2; rr++) {
            int r = 2 * w + rr;
            float sm = 0.0f;
#pragma unroll
            for (int c = 0; c < 4; c++) {
                float x = s->f[r][lane + 32 * c];
                sm += x * x;
            }
#pragma unroll
            for (int o = 16; o > 0; o >>= 1) sm += __shfl_xor_sync(0xffffffffu, sm, o);
            if (lane == 0) s->invn[r] = 1.0f / fmaxf(sqrtf(sm), 1e-12f);
        }
    }
    __syncthreads();

    // per-class scalars
    if (tid < KC) {
        float sm = 0.0f;
#pragma unroll
        for (int q = 0; q < 8; q++) sm += s->musq[q][tid];
        s->invmu[tid] = 1.0f / fmaxf(sqrtf(sm), 1e-12f);
        float r = rho[tid];
        float kap = fmaxf(softplus_precise(r), 1e-6f);
        s->kap[tid] = kap;
        float logI = (kap < 1e-3f)
                   ? 63.0f * logf(kap * 0.5f + 1e-12f) - LGAMMA64F
                   : kap - 0.5f * logf(6.283185307179586f * kap + 1e-12f);
        s->lc[tid] = -63.0f * logf(kap + 1e-12f) - 64.0f * LOG2PIF - logI;
    }
    if (tid < NB) atomicAdd(&g_counts[s->lab[tid]], 1.0f);
    __syncthreads();

    // L = logC + kappa*invmu*invn*(f . mu_raw); 8 groups x 4 samples
    int g = tid >> 6;
    int k = tid & 63;
    {
        float acc0 = 0.f, acc1 = 0.f, acc2 = 0.f, acc3 = 0.f;
        const float4* f0 = (const float4*)&s->f[g * 4 + 0][0];
        const float4* f1 = (const float4*)&s->f[g * 4 + 1][0];
        const float4* f2 = (const float4*)&s->f[g * 4 + 2][0];
        const float4* f3 = (const float4*)&s->f[g * 4 + 3][0];
        const float* mrow = &s->mus[k * MPAD];
#pragma unroll
        for (int d4 = 0; d4 < DD / 4; d4++) {
            float m0 = mrow[4 * d4 + 0];
            float m1 = mrow[4 * d4 + 1];
            float m2 = mrow[4 * d4 + 2];
            float m3 = mrow[4 * d4 + 3];
            float4 x0 = f0[d4], x1 = f1[d4], x2 = f2[d4], x3 = f3[d4];
            acc0 += m0 * x0.x + m1 * x0.y + m2 * x0.z + m3 * x0.w;
            acc1 += m0 * x1.x + m1 * x1.y + m2 * x1.z + m3 * x1.w;
            acc2 += m0 * x2.x + m1 * x2.y + m2 * x2.z + m3 * x2.w;
            acc3 += m0 * x3.x + m1 * x3.y + m2 * x3.z + m3 * x3.w;
        }
        float sk = s->kap[k] * s->invmu[k], lc = s->lc[k];
        s->L[g * 4 + 0][k] = lc + sk * s->invn[g * 4 + 0] * acc0;
        s->L[g * 4 + 1][k] = lc + sk * s->invn[g * 4 + 1] * acc1;
        s->L[g * 4 + 2][k] = lc + sk * s->invn[g * 4 + 2] * acc2;
        s->L[g * 4 + 3][k] = lc + sk * s->invn[g * 4 + 3] * acc3;
    }
    __syncthreads();

    // numer + dsum: thread -> (n = tid>>4, k-quad); two v4 REDG
    {
        int n = tid >> 4;
        int k0 = (tid & 15) * 4;
        float4 Lv  = *(const float4*)&s->L[n][k0];
        float4 lcv = *(const float4*)&s->lc[k0];
        float Li = s->L[n][s->lab[n]];
        float Lr[4] = {Lv.x, Lv.y, Lv.z, Lv.w};
        float lcr[4] = {lcv.x, lcv.y, lcv.z, lcv.w};
        float vn[4], vd[4];
#pragma unroll
        for (int c = 0; c < 4; c++) {
            float x = Lr[c] - Li;
            float t = __expf(-fabsf(x));
            vn[c] = LN2F - (log1p_poly(t) + fmaxf(x, 0.0f));
            vd[c] = Lr[c] - lcr[c];           // kap_j * (fhat . mu_j)
        }
        int row = s->lab[n] * KC + k0;
        red_v4(&g_numer[row], vn[0], vn[1], vn[2], vn[3]);
        red_v4(&g_dsum[row],  vd[0], vd[1], vd[2], vd[3]);
    }

    // ---------------- last-arriver election (NO spin barrier) ----------------
    __threadfence();            // release: all REDG/atomics visible device-wide
    __syncthreads();
    if (tid == 0) s->is_last = (atomicAdd(&g_arrive, 1) == GRID - 1);
    __syncthreads();
    if (!s->is_last) return;    // 127 blocks exit immediately
    __threadfence();            // acquire

    // ================ single-block epilogue (everything is globally visible) ================
    float* numr2 = &s->f[0][0];       // [64][64] overlay (16KB)
    float* dsum2 = &s->mus[0];        // [64][64] overlay (first 16KB of mus)
    float* ep    = &s->L[0][0];
    float* cs    = ep;                // 64
    float* ics   = ep + 64;           // 64
    float* Ei    = ep + 128;          // 64  (kap_i * dotm[i][i])
    float* zif   = ep + 192;          // 64  (1.0 if count==0)
    float* wr    = ep + 256;          // 16 warp partials rank
    float* wj    = ep + 272;          // 16 warp partials js

    // bulk load both matrices (high MLP)
    {
        const float4* gn = (const float4*)g_numer;
        const float4* gd = (const float4*)g_dsum;
        float4* dn = (float4*)numr2;
        float4* dd = (float4*)dsum2;
        dn[tid] = gn[tid]; dn[tid + NT] = gn[tid + NT];
        dd[tid] = gd[tid]; dd[tid + NT] = gd[tid + NT];
    }
    int zpred = 0;
    if (tid < KC) {
        float c = g_counts[tid];
        cs[tid] = c;
        ics[tid] = 1.0f / fmaxf(c, 1.0f);
        zif[tid] = (c == 0.0f) ? 1.0f : 0.0f;
        zpred = (c == 0.0f);
    }
    int anyzero = __syncthreads_or(zpred);

    // per-row E_si; reset global state (data now in smem)
    if (tid < KC)
        Ei[tid] = (zif[tid] != 0.0f) ? s->kap[tid] : dsum2[tid * KC + tid] * ics[tid];
    {
        float4 z4 = make_float4(0.f, 0.f, 0.f, 0.f);
        float4* gn = (float4*)g_numer;
        float4* gd = (float4*)g_dsum;
        gn[tid] = z4; gn[tid + NT] = z4;
        gd[tid] = z4; gd[tid + NT] = z4;
    }
    if (tid < KC) g_counts[tid] = 0.0f;
    if (tid == 0) g_arrive = 0;
    __syncthreads();

    // map: 8 pairs per thread
    float r_acc = 0.0f, j_acc = 0.0f;
#pragma unroll
    for (int c = 0; c < 8; c++) {
        int p = tid + NT * c;
        int i = p >> 6, j = p & 63;
        float w = (i == j) ? 0.0f : fabsf((float)(i - j));
        bool zpi = false, zpj = false;
        float du = 0.0f;
        if (anyzero) {
            zpi = (zif[i] != 0.0f);
            zpj = (zif[j] != 0.0f);
            if (zpi || zpj) {
                // slow correct fallback: mu_i . mu_j from global (astronomically rare)
                float dd = 0.0f;
                for (int d = 0; d < DD; d++)
                    dd += musp[i * DD + d] * musp[j * DD + d];
                du = dd * s->invmu[i] * s->invmu[j];
            }
        }
        // rank
        float diff = zpi ? (s->kap[i] - s->kap[j] * du)
                         : (Ei[i] - dsum2[i * KC + j] * ics[i]);
        if (i != j) r_acc += fmaxf(0.5f * w - diff, 0.0f) * ics[i];
        // js
        if (zpi || zpj) {
            float ki = s->kap[i], kj = s->kap[j];
            float kci = fmaxf(ki, 1e-8f), kcj = fmaxf(kj, 1e-8f);
            float Ai = (kci > 50.0f) ? (1.0f - 127.0f / (2.0f * kci)) : (kci / 128.0f);
            float Aj = (kcj > 50.0f) ? (1.0f - 127.0f / (2.0f * kcj)) : (kcj / 128.0f);
            j_acc += w * 0.5f * (Ai * (ki - kj * du) + Aj * (kj - ki * du));
        } else {
            j_acc += w * numr2[i * KC + j] * ics[i];   // symmetry-folded JS
        }
    }

    // block reduction (16 warps)
    int wid = tid >> 5, lane = tid & 31;
#pragma unroll
    for (int o = 16; o > 0; o >>= 1) {
        r_acc += __shfl_xor_sync(0xffffffffu, r_acc, o);
        j_acc += __shfl_xor_sync(0xffffffffu, j_acc, o);
    }
    if (lane == 0) { wr[wid] = r_acc; wj[wid] = j_acc; }
    __syncthreads();
    if (tid < 16) {
        float r = wr[tid], jj = wj[tid];
#pragma unroll
        for (int o = 8; o > 0; o >>= 1) {
            r  += __shfl_xor_sync(0xffffu, r, o);
            jj += __shfl_xor_sync(0xffffu, jj, o);
        }
        if (tid == 0)
            out[0] = r / (4096.0f + 1e-9f) + jj / (87360.0f + 1e-9f);
    }
}

extern "C" void kernel_launch(void* const* d_in, const int* in_sizes, int n_in,
                              void* d_out, int out_size) {
    const float* features  = (const float*)d_in[0];
    const float* mus_param = (const float*)d_in[1];
    const float* rho_kappa = (const float*)d_in[2];
    const int*   labels32  = (const int*)d_in[3];
    float* out = (float*)d_out;

    cudaFuncSetAttribute(k_fused, cudaFuncAttributeMaxDynamicSharedMemorySize,
                         (int)sizeof(Smem));
    k_fused<<<GRID, NT, sizeof(Smem)>>>(features, mus_param, rho_kappa, labels32, out);
}